// round 5
// baseline (speedup 1.0000x reference)
#include <cuda_runtime.h>

// MessagePassing tree DP on a deterministic 4-ary heap tree.
// B=64, C=2, L=4096. Child s in [1,L) has parent (s-1)>>2.
// Level starts: (4^k-1)/3 = 0,1,5,21,85,341,1365 (leaves clipped at 4096).
//
// Two kernels:
//  1) pack_kernel: gather the 4095 needed transition 2x2 blocks ONCE into a
//     compact __device__ table g_packed[s] = transitions[s][(s-1)>>2][:][:].
//     (All 64 batch-CTAs previously redid this identical scattered gather.)
//  2) mp_tree_kernel: one CTA per batch. Loads g_packed COALESCED into shared
//     (L2-hit), stages parent emissions into shared, then runs the 6-level DP
//     as a pure shared-memory dependency chain. No global loads on the
//     critical path, no big register arrays (R4 lesson: 12xfloat4 spills).

#define LNODES 4096
#define NT 512

__device__ float4 g_packed[LNODES];   // 64 KB static device scratch (allowed)

__global__ void pack_kernel(const float* __restrict__ tr)  // [L, L, 2, 2]
{
    const int s = blockIdx.x * blockDim.x + threadIdx.x;   // 0..4095
    if (s >= 1 && s < LNODES) {
        const int p = (s - 1) >> 2;
        g_packed[s] = __ldg((const float4*)(tr + ((size_t)s * LNODES + p) * 4));
    }
}

__device__ __forceinline__ float lse2(float a, float b) {
    float m = fmaxf(a, b);
    return m + __logf(1.0f + __expf(-fabsf(a - b)));
}

__global__ __launch_bounds__(NT, 1)
void mp_tree_kernel(const float* __restrict__ em,   // [B, 2, L]
                    float* __restrict__ out)        // [B, 2, L]
{
    // dynamic shared: trs 64KB | msg0 16KB | msg1 16KB | em0 4KB | em1 4KB
    extern __shared__ char smem_raw[];
    float4* trs  = (float4*)smem_raw;                       // [4096]
    float*  msg0 = (float*)(smem_raw + LNODES * 16);        // [4096]
    float*  msg1 = msg0 + LNODES;                           // [4096]
    float*  em0  = msg1 + LNODES;                           // [1024]
    float*  em1  = em0 + 1024;                              // [1024]

    const int   tid = threadIdx.x;
    const int   b   = blockIdx.x;
    const float* eb = em + (size_t)b * 2 * LNODES;

    // ---- Phase 0: coalesced staging (all latency overlapped) ----
    #pragma unroll
    for (int i = 0; i < 8; i++) {                 // 4096 float4 of transitions
        const int j = i * NT + tid;
        trs[j] = g_packed[j];
    }
    #pragma unroll
    for (int i = 0; i < 2; i++) {                 // parent emissions p<1024
        const int p = i * NT + tid;
        em0[p] = __ldg(eb + p);
        em1[p] = __ldg(eb + LNODES + p);
    }
    if (tid == 0) { msg0[0] = 0.0f; msg1[0] = 0.0f; }
    __syncthreads();

    // ---- Phase 1: 6-level sweep, pure shared-memory chain ----
    constexpr int starts[8] = {0, 1, 5, 21, 85, 341, 1365, 5461};
    constexpr int iters[8]  = {0, 1, 1, 1, 1, 2, 6, 0};

    #pragma unroll
    for (int lev = 1; lev <= 6; lev++) {
        const int s1 = (starts[lev + 1] < LNODES) ? starts[lev + 1] : LNODES;
        #pragma unroll
        for (int i = 0; i < iters[lev]; i++) {
            const int s = starts[lev] + i * NT + tid;
            if (s < s1) {
                const int p  = (s - 1) >> 2;
                const float l0 = em0[p] + msg0[p];
                const float l1 = em1[p] + msg1[p];
                const float4 t = trs[s];
                msg0[s] = lse2(l0 + t.x, l1 + t.y);
                msg1[s] = lse2(l0 + t.z, l1 + t.w);
            }
        }
        __syncthreads();
    }

    // ---- Phase 2: vectorized writeback (covers poisoned d_out; root = 0) ----
    float4* ob0 = (float4*)(out + (size_t)b * 2 * LNODES);
    float4* ob1 = (float4*)(out + (size_t)b * 2 * LNODES + LNODES);
    const float4* m0 = (const float4*)msg0;
    const float4* m1 = (const float4*)msg1;
    #pragma unroll
    for (int i = 0; i < 2; i++) {
        const int j = i * NT + tid;               // 1024 float4 per class
        ob0[j] = m0[j];
        ob1[j] = m1[j];
    }
}

extern "C" void kernel_launch(void* const* d_in, const int* in_sizes, int n_in,
                              void* d_out, int out_size) {
    const float* em = (const float*)d_in[0];  // emissions   [64, 2, 4096] f32
    const float* tr = (const float*)d_in[1];  // transitions [4096,4096,2,2] f32
    (void)in_sizes; (void)n_in; (void)out_size;

    const int smem_bytes = LNODES * 16 + LNODES * 8 + 2048 * 4;  // 104 KB
    static bool attr_set = false;
    if (!attr_set) {
        cudaFuncSetAttribute(mp_tree_kernel,
                             cudaFuncAttributeMaxDynamicSharedMemorySize,
                             smem_bytes);
        attr_set = true;
    }

    pack_kernel<<<32, 128>>>(tr);
    mp_tree_kernel<<<64, NT, smem_bytes>>>(em, (float*)d_out);
}